// round 2
// baseline (speedup 1.0000x reference)
#include <cuda_runtime.h>
#include <cstdint>

#define C 128                 // Cin == Cout == 128
#define MAX_N 50176           // padded 50000
#define EPS 1e-6f

// Scratch (device globals; no allocation allowed)
__device__ float g_y[MAX_N * C];      // y = x @ W
__device__ float g_sdeg[MAX_N];
__device__ float g_ddeg[MAX_N];

// ---------------------------------------------------------------------------
// Kernel 1: out[n*C+c] = bias[c]; zero degree arrays
// ---------------------------------------------------------------------------
__global__ void init_kernel(float* __restrict__ out, const float* __restrict__ bias, int N) {
    int i = blockIdx.x * blockDim.x + threadIdx.x;
    int total = N * C;
    if (i < total) out[i] = bias[i & (C - 1)];
    if (i < N) { g_sdeg[i] = 0.0f; g_ddeg[i] = 0.0f; }
}

// ---------------------------------------------------------------------------
// Kernel 2: degree counts (spread-address atomics, cheap)
// ---------------------------------------------------------------------------
__global__ void deg_kernel(const int* __restrict__ ei, int E) {
    int e = blockIdx.x * blockDim.x + threadIdx.x;
    if (e >= E) return;
    int s = ei[e];
    int d = ei[E + e];
    atomicAdd(&g_sdeg[s], 1.0f);
    atomicAdd(&g_ddeg[d], 1.0f);
}

// ---------------------------------------------------------------------------
// Kernel 3: y = x @ W   (N x 128) @ (128 x 128), fp32
// Block: 256 threads, tile 128 rows x 128 cols, 8x8 register tile per thread.
// ---------------------------------------------------------------------------
__global__ __launch_bounds__(256) void gemm_kernel(const float* __restrict__ x,
                                                   const float* __restrict__ w,
                                                   int N) {
    __shared__ float sA[8][C + 4];   // [k][row]
    __shared__ float sB[8][C];       // [k][col]

    const int row0 = blockIdx.x * 128;
    const int tx = threadIdx.x;
    const int tr = (tx & 15) * 8;    // row offset in tile (0..120)
    const int tc = (tx >> 4) * 8;    // col offset in tile (0..120)

    float acc[8][8];
#pragma unroll
    for (int i = 0; i < 8; i++)
#pragma unroll
        for (int j = 0; j < 8; j++) acc[i][j] = 0.0f;

    for (int k0 = 0; k0 < C; k0 += 8) {
        // load A tile: 128 rows x 8 k-cols (1024 floats / 256 threads = 4 each)
#pragma unroll
        for (int t = 0; t < 4; t++) {
            int i = tx + t * 256;
            int r = i >> 3, kk = i & 7;
            int gr = row0 + r;
            sA[kk][r] = (gr < N) ? x[gr * C + k0 + kk] : 0.0f;
        }
        // load B tile: 8 k-rows x 128 cols
#pragma unroll
        for (int t = 0; t < 4; t++) {
            int i = tx + t * 256;
            int kk = i >> 7, c = i & 127;
            sB[kk][c] = w[(k0 + kk) * C + c];
        }
        __syncthreads();
#pragma unroll
        for (int kk = 0; kk < 8; kk++) {
            float a[8], b[8];
#pragma unroll
            for (int i = 0; i < 8; i++) a[i] = sA[kk][tr + i];
#pragma unroll
            for (int j = 0; j < 8; j++) b[j] = sB[kk][tc + j];
#pragma unroll
            for (int i = 0; i < 8; i++)
#pragma unroll
                for (int j = 0; j < 8; j++) acc[i][j] += a[i] * b[j];
        }
        __syncthreads();
    }

#pragma unroll
    for (int i = 0; i < 8; i++) {
        int gr = row0 + tr + i;
        if (gr < N) {
            float4* dst = reinterpret_cast<float4*>(&g_y[gr * C + tc]);
            dst[0] = make_float4(acc[i][0], acc[i][1], acc[i][2], acc[i][3]);
            dst[1] = make_float4(acc[i][4], acc[i][5], acc[i][6], acc[i][7]);
        }
    }
}

// ---------------------------------------------------------------------------
// Kernel 4: scatter  out[dst] += y[src] * norm(src,dst)
// One warp per edge; lane l handles channels [4l, 4l+4) via red.global.add.v4.f32
// ---------------------------------------------------------------------------
__global__ __launch_bounds__(256) void scatter_kernel(const int* __restrict__ ei,
                                                      float* __restrict__ out,
                                                      int E) {
    int gw = (blockIdx.x * blockDim.x + threadIdx.x) >> 5;   // global warp id = edge id
    int lane = threadIdx.x & 31;
    if (gw >= E) return;

    int s = ei[gw];
    int d = ei[E + gw];
    float norm = rsqrtf(g_sdeg[s] + EPS) * rsqrtf(g_ddeg[d] + EPS);

    const float4* ys = reinterpret_cast<const float4*>(g_y + (size_t)s * C);
    float4 v = ys[lane];
    v.x *= norm; v.y *= norm; v.z *= norm; v.w *= norm;

    float* dp = out + (size_t)d * C + lane * 4;
    asm volatile("red.global.add.v4.f32 [%0], {%1, %2, %3, %4};"
                 :: "l"(dp), "f"(v.x), "f"(v.y), "f"(v.z), "f"(v.w)
                 : "memory");
}

// ---------------------------------------------------------------------------
extern "C" void kernel_launch(void* const* d_in, const int* in_sizes, int n_in,
                              void* d_out, int out_size) {
    const float* x    = (const float*)d_in[0];
    const int*   ei   = (const int*)d_in[1];
    const float* w    = (const float*)d_in[2];
    const float* bias = (const float*)d_in[3];
    float*       out  = (float*)d_out;

    const int N = in_sizes[0] / C;
    const int E = in_sizes[1] / 2;

    // 1) init out with bias, zero degree arrays
    {
        int total = N * C;
        int threads = 256;
        int blocks = (total + threads - 1) / threads;
        init_kernel<<<blocks, threads>>>(out, bias, N);
    }
    // 2) degree counts
    {
        int threads = 256;
        int blocks = (E + threads - 1) / threads;
        deg_kernel<<<blocks, threads>>>(ei, E);
    }
    // 3) y = x @ W
    {
        int blocks = (N + 127) / 128;
        gemm_kernel<<<blocks, 256>>>(x, w, N);
    }
    // 4) scatter-add into out
    {
        long long total_threads = (long long)E * 32;
        int threads = 256;
        int blocks = (int)((total_threads + threads - 1) / threads);
        scatter_kernel<<<blocks, threads>>>(ei, out, E);
    }
}

// round 3
// speedup vs baseline: 1.0972x; 1.0972x over previous
#include <cuda_runtime.h>
#include <cstdint>

#define C 128                 // Cin == Cout == 128
#define MAX_N 50176           // padded 50000
#define MAX_E 1050000
#define EPS 1e-6f

// Scratch (device globals; no allocation allowed)
__device__ float g_y[MAX_N * C];       // y = (x @ W) * src_inv[row]
__device__ int   g_sdeg[MAX_N];
__device__ int   g_ddeg[MAX_N];
__device__ int   g_off[MAX_N];         // exclusive prefix of ddeg
__device__ int   g_cur[MAX_N];         // fill cursors
__device__ int   g_csr[MAX_E];         // src ids grouped by dst

// ---------------------------------------------------------------------------
// K1: zero degree/cursor arrays
// ---------------------------------------------------------------------------
__global__ void zero_kernel(int N) {
    int i = blockIdx.x * blockDim.x + threadIdx.x;
    if (i < N) { g_sdeg[i] = 0; g_ddeg[i] = 0; g_cur[i] = 0; }
}

// ---------------------------------------------------------------------------
// K2: degree counts
// ---------------------------------------------------------------------------
__global__ void deg_kernel(const int* __restrict__ ei, int E) {
    int e = blockIdx.x * blockDim.x + threadIdx.x;
    if (e >= E) return;
    atomicAdd(&g_sdeg[ei[e]], 1);
    atomicAdd(&g_ddeg[ei[E + e]], 1);
}

// ---------------------------------------------------------------------------
// K3: exclusive prefix scan of g_ddeg -> g_off  (single block, shfl-based)
// ---------------------------------------------------------------------------
__global__ __launch_bounds__(1024) void scan_kernel(int N) {
    __shared__ int warp_tot[32];
    __shared__ int warp_pre[32];
    __shared__ int s_running;
    const int tid = threadIdx.x;
    const int lane = tid & 31;
    const int wid = tid >> 5;
    if (tid == 0) s_running = 0;
    __syncthreads();

    for (int base = 0; base < N; base += 1024) {
        int i = base + tid;
        int v = (i < N) ? g_ddeg[i] : 0;
        // warp inclusive scan
        int incl = v;
#pragma unroll
        for (int d = 1; d < 32; d <<= 1) {
            int t = __shfl_up_sync(0xffffffff, incl, d);
            if (lane >= d) incl += t;
        }
        if (lane == 31) warp_tot[wid] = incl;
        __syncthreads();
        if (wid == 0) {
            int wv = warp_tot[lane];
            int wi = wv;
#pragma unroll
            for (int d = 1; d < 32; d <<= 1) {
                int t = __shfl_up_sync(0xffffffff, wi, d);
                if (lane >= d) wi += t;
            }
            warp_pre[lane] = wi - wv;   // exclusive warp prefix
            if (lane == 31) warp_tot[0] = wi;  // chunk total
        }
        __syncthreads();
        int running = s_running;
        if (i < N) g_off[i] = running + warp_pre[wid] + incl - v;
        int chunk_total = warp_tot[0];
        __syncthreads();
        if (tid == 0) s_running = running + chunk_total;
        __syncthreads();
    }
}

// ---------------------------------------------------------------------------
// K4: fill CSR (group src ids by dst)
// ---------------------------------------------------------------------------
__global__ void fill_kernel(const int* __restrict__ ei, int E) {
    int e = blockIdx.x * blockDim.x + threadIdx.x;
    if (e >= E) return;
    int s = ei[e];
    int d = ei[E + e];
    int pos = g_off[d] + atomicAdd(&g_cur[d], 1);
    g_csr[pos] = s;
}

// ---------------------------------------------------------------------------
// K5: y = (x @ W) * rsqrt(sdeg + EPS)   (N x 128) @ (128 x 128), fp32
// ---------------------------------------------------------------------------
__global__ __launch_bounds__(256) void gemm_kernel(const float* __restrict__ x,
                                                   const float* __restrict__ w,
                                                   int N) {
    __shared__ float sA[8][C + 4];   // [k][row]
    __shared__ float sB[8][C];       // [k][col]

    const int row0 = blockIdx.x * 128;
    const int tx = threadIdx.x;
    const int tr = (tx & 15) * 8;    // row offset in tile
    const int tc = (tx >> 4) * 8;    // col offset in tile

    float acc[8][8];
#pragma unroll
    for (int i = 0; i < 8; i++)
#pragma unroll
        for (int j = 0; j < 8; j++) acc[i][j] = 0.0f;

    for (int k0 = 0; k0 < C; k0 += 8) {
#pragma unroll
        for (int t = 0; t < 4; t++) {
            int i = tx + t * 256;
            int r = i >> 3, kk = i & 7;
            int gr = row0 + r;
            sA[kk][r] = (gr < N) ? x[gr * C + k0 + kk] : 0.0f;
        }
#pragma unroll
        for (int t = 0; t < 4; t++) {
            int i = tx + t * 256;
            int kk = i >> 7, c = i & 127;
            sB[kk][c] = w[(k0 + kk) * C + c];
        }
        __syncthreads();
#pragma unroll
        for (int kk = 0; kk < 8; kk++) {
            float a[8], b[8];
#pragma unroll
            for (int i = 0; i < 8; i++) a[i] = sA[kk][tr + i];
#pragma unroll
            for (int j = 0; j < 8; j++) b[j] = sB[kk][tc + j];
#pragma unroll
            for (int i = 0; i < 8; i++)
#pragma unroll
                for (int j = 0; j < 8; j++) acc[i][j] += a[i] * b[j];
        }
        __syncthreads();
    }

#pragma unroll
    for (int i = 0; i < 8; i++) {
        int gr = row0 + tr + i;
        if (gr < N) {
            float sc = rsqrtf((float)g_sdeg[gr] + EPS);
            float4* dst = reinterpret_cast<float4*>(&g_y[gr * C + tc]);
            dst[0] = make_float4(acc[i][0] * sc, acc[i][1] * sc, acc[i][2] * sc, acc[i][3] * sc);
            dst[1] = make_float4(acc[i][4] * sc, acc[i][5] * sc, acc[i][6] * sc, acc[i][7] * sc);
        }
    }
}

// ---------------------------------------------------------------------------
// K6: gather  out[n] = dst_inv[n] * sum_{e: dst=n} y[src_e] + bias
// One warp per dst node; lane l holds channels [4l, 4l+4) as float4.
// ---------------------------------------------------------------------------
__global__ __launch_bounds__(256) void gather_kernel(float* __restrict__ out,
                                                     const float* __restrict__ bias,
                                                     int N) {
    int n = (blockIdx.x * blockDim.x + threadIdx.x) >> 5;
    int lane = threadIdx.x & 31;
    if (n >= N) return;

    int off = g_off[n];
    int cnt = g_ddeg[n];

    const float4* yp = reinterpret_cast<const float4*>(g_y);
    float4 acc = make_float4(0.f, 0.f, 0.f, 0.f);

    int i = 0;
    for (; i + 4 <= cnt; i += 4) {
        int s0 = __ldg(&g_csr[off + i + 0]);
        int s1 = __ldg(&g_csr[off + i + 1]);
        int s2 = __ldg(&g_csr[off + i + 2]);
        int s3 = __ldg(&g_csr[off + i + 3]);
        float4 v0 = yp[(size_t)s0 * 32 + lane];
        float4 v1 = yp[(size_t)s1 * 32 + lane];
        float4 v2 = yp[(size_t)s2 * 32 + lane];
        float4 v3 = yp[(size_t)s3 * 32 + lane];
        acc.x += v0.x + v1.x + v2.x + v3.x;
        acc.y += v0.y + v1.y + v2.y + v3.y;
        acc.z += v0.z + v1.z + v2.z + v3.z;
        acc.w += v0.w + v1.w + v2.w + v3.w;
    }
    for (; i < cnt; i++) {
        int s = __ldg(&g_csr[off + i]);
        float4 v = yp[(size_t)s * 32 + lane];
        acc.x += v.x; acc.y += v.y; acc.z += v.z; acc.w += v.w;
    }

    float dinv = rsqrtf((float)cnt + EPS);
    const float4 b = reinterpret_cast<const float4*>(bias)[lane];
    float4 r = make_float4(acc.x * dinv + b.x, acc.y * dinv + b.y,
                           acc.z * dinv + b.z, acc.w * dinv + b.w);
    reinterpret_cast<float4*>(out)[(size_t)n * 32 + lane] = r;
}

// ---------------------------------------------------------------------------
extern "C" void kernel_launch(void* const* d_in, const int* in_sizes, int n_in,
                              void* d_out, int out_size) {
    const float* x    = (const float*)d_in[0];
    const int*   ei   = (const int*)d_in[1];
    const float* w    = (const float*)d_in[2];
    const float* bias = (const float*)d_in[3];
    float*       out  = (float*)d_out;

    const int N = in_sizes[0] / C;
    const int E = in_sizes[1] / 2;

    zero_kernel<<<(N + 255) / 256, 256>>>(N);
    deg_kernel<<<(E + 255) / 256, 256>>>(ei, E);
    scan_kernel<<<1, 1024>>>(N);
    fill_kernel<<<(E + 255) / 256, 256>>>(ei, E);
    gemm_kernel<<<(N + 127) / 128, 256>>>(x, w, N);
    {
        long long total_threads = (long long)N * 32;
        int blocks = (int)((total_threads + 255) / 256);
        gather_kernel<<<blocks, 256>>>(out, bias, N);
    }
}

// round 5
// speedup vs baseline: 1.8900x; 1.7226x over previous
#include <cuda_runtime.h>
#include <cuda_bf16.h>
#include <cstdint>

#define C 128
#define MAX_N 50176
#define MAX_E 1050000
#define EPS 1e-6f
#define SX 136                      // padded bf16 row stride (272B: conflict-free ldmatrix)

// ---------------------------------------------------------------------------
// Device scratch
// ---------------------------------------------------------------------------
__device__ __align__(16) float g_y[MAX_N * C];     // (x @ W) * src_inv[row]
__device__ int   g_sdeg[MAX_N];
__device__ int   g_ddeg[MAX_N];
__device__ int   g_off[MAX_N];
__device__ int   g_cur[MAX_N];
__device__ int   g_csr[MAX_E];
__device__ int   g_btot[64];
__device__ int   g_bpre[64];
// W transposed (Wt[n][k]) as bf16 hi/lo, padded stride SX
__device__ __align__(16) unsigned short g_wt_hi[128 * SX];
__device__ __align__(16) unsigned short g_wt_lo[128 * SX];

// ---------------------------------------------------------------------------
// K0: prep Wt[n][k] = W[k][n] -> bf16 hi/lo, padded
// ---------------------------------------------------------------------------
__global__ void prep_w_kernel(const float* __restrict__ w) {
    int tid = blockIdx.x * blockDim.x + threadIdx.x;   // 128*SX threads
    if (tid >= 128 * SX) return;
    int n = tid / SX, k = tid % SX;
    unsigned short h = 0, l = 0;
    if (k < 128) {
        float f = w[k * 128 + n];
        __nv_bfloat16 hb = __float2bfloat16_rn(f);
        __nv_bfloat16 lb = __float2bfloat16_rn(f - __bfloat162float(hb));
        h = __bfloat16_as_ushort(hb);
        l = __bfloat16_as_ushort(lb);
    }
    g_wt_hi[tid] = h;
    g_wt_lo[tid] = l;
}

// ---------------------------------------------------------------------------
// K1: zero degree arrays
// ---------------------------------------------------------------------------
__global__ void zero_kernel(int N) {
    int i = blockIdx.x * blockDim.x + threadIdx.x;
    if (i < N) { g_sdeg[i] = 0; g_ddeg[i] = 0; }
}

// ---------------------------------------------------------------------------
// K2: degree counts
// ---------------------------------------------------------------------------
__global__ void deg_kernel(const int* __restrict__ ei, int E) {
    int e = blockIdx.x * blockDim.x + threadIdx.x;
    if (e >= E) return;
    atomicAdd(&g_sdeg[ei[e]], 1);
    atomicAdd(&g_ddeg[ei[E + e]], 1);
}

// ---------------------------------------------------------------------------
// K3a/b/c: multi-block exclusive scan of g_ddeg -> g_off (and g_cur)
// ---------------------------------------------------------------------------
__global__ __launch_bounds__(1024) void scanA_kernel(int N) {
    __shared__ int wt[32], wp[32];
    int tid = threadIdx.x, lane = tid & 31, wid = tid >> 5;
    int i = blockIdx.x * 1024 + tid;
    int v = (i < N) ? g_ddeg[i] : 0;
    int incl = v;
#pragma unroll
    for (int d = 1; d < 32; d <<= 1) {
        int t = __shfl_up_sync(0xffffffff, incl, d);
        if (lane >= d) incl += t;
    }
    if (lane == 31) wt[wid] = incl;
    __syncthreads();
    if (wid == 0) {
        int wv = wt[lane];
        int wi = wv;
#pragma unroll
        for (int d = 1; d < 32; d <<= 1) {
            int t = __shfl_up_sync(0xffffffff, wi, d);
            if (lane >= d) wi += t;
        }
        wp[lane] = wi - wv;
        if (lane == 31) g_btot[blockIdx.x] = wi;
    }
    __syncthreads();
    if (i < N) g_off[i] = wp[wid] + incl - v;
}

__global__ void scanB_kernel(int nb) {
    __shared__ int s[64];
    int tid = threadIdx.x;
    s[tid] = (tid < nb) ? g_btot[tid] : 0;
    __syncthreads();
    if (tid == 0) {
        int acc = 0;
        for (int j = 0; j < nb; j++) { int t = s[j]; s[j] = acc; acc += t; }
    }
    __syncthreads();
    if (tid < nb) g_bpre[tid] = s[tid];
}

__global__ void scanC_kernel(int N) {
    int i = blockIdx.x * blockDim.x + threadIdx.x;
    if (i >= N) return;
    int v = g_off[i] + g_bpre[i >> 10];
    g_off[i] = v;
    g_cur[i] = v;
}

// ---------------------------------------------------------------------------
// K4: fill CSR (cursors pre-initialized to offsets)
// ---------------------------------------------------------------------------
__global__ void fill_kernel(const int* __restrict__ ei, int E) {
    int e = blockIdx.x * blockDim.x + threadIdx.x;
    if (e >= E) return;
    int s = ei[e];
    int d = ei[E + e];
    int pos = atomicAdd(&g_cur[d], 1);
    g_csr[pos] = s;
}

// ---------------------------------------------------------------------------
// K5: tensor-core GEMM via mma.sync (HMMA, baseline ISA — no 'a' feature)
//     y = (x @ W) * rsqrt(sdeg+EPS), bf16 hi/lo x3 passes, fp32 accum.
//     CTA: 128 rows x 128 cols, 8 warps = 2(m) x 4(n), warp tile 64x32.
// ---------------------------------------------------------------------------
#define SMEM_GEMM (4 * 128 * SX * 2)   // xs_hi, xs_lo, wt_hi, wt_lo = 139264 B

__device__ __forceinline__ void ldsm_x4(uint32_t addr, uint32_t& r0, uint32_t& r1,
                                        uint32_t& r2, uint32_t& r3) {
    asm volatile("ldmatrix.sync.aligned.m8n8.x4.shared.b16 {%0,%1,%2,%3}, [%4];"
                 : "=r"(r0), "=r"(r1), "=r"(r2), "=r"(r3) : "r"(addr));
}

__device__ __forceinline__ void mma16816(float* c, const uint32_t* a, const uint32_t* b) {
    asm volatile(
        "mma.sync.aligned.m16n8k16.row.col.f32.bf16.bf16.f32 "
        "{%0,%1,%2,%3}, {%4,%5,%6,%7}, {%8,%9}, {%0,%1,%2,%3};"
        : "+f"(c[0]), "+f"(c[1]), "+f"(c[2]), "+f"(c[3])
        : "r"(a[0]), "r"(a[1]), "r"(a[2]), "r"(a[3]), "r"(b[0]), "r"(b[1]));
}

__global__ __launch_bounds__(256, 1) void gemm_tc_kernel(const float* __restrict__ x,
                                                         int N) {
    extern __shared__ __align__(16) char smem[];
    unsigned short* xs_hi = reinterpret_cast<unsigned short*>(smem);
    unsigned short* xs_lo = xs_hi + 128 * SX;
    unsigned short* ws_hi = xs_lo + 128 * SX;
    unsigned short* ws_lo = ws_hi + 128 * SX;

    const int tid = threadIdx.x;
    const int lane = tid & 31;
    const int wid = tid >> 5;
    const int row0 = blockIdx.x * 128;

    // ---- stage W (copy padded hi/lo images) ----
    {
        const uint4* sH = reinterpret_cast<const uint4*>(g_wt_hi);
        const uint4* sL = reinterpret_cast<const uint4*>(g_wt_lo);
        uint4* dH = reinterpret_cast<uint4*>(ws_hi);
        uint4* dL = reinterpret_cast<uint4*>(ws_lo);
        const int n16 = 128 * SX / 8;   // 2176 uint4
        for (int i = tid; i < n16; i += 256) { dH[i] = sH[i]; dL[i] = sL[i]; }
    }

    // ---- stage x tile -> bf16 hi/lo (thread = half row) ----
    {
        int r = tid >> 1, h = tid & 1;
        int gr = row0 + r;
        const float4* xrow = reinterpret_cast<const float4*>(x + (size_t)gr * 128 + h * 64);
        uint4* dH = reinterpret_cast<uint4*>(xs_hi + r * SX + h * 64);
        uint4* dL = reinterpret_cast<uint4*>(xs_lo + r * SX + h * 64);
#pragma unroll
        for (int g = 0; g < 8; g++) {
            float4 f0, f1;
            if (gr < N) { f0 = xrow[2 * g]; f1 = xrow[2 * g + 1]; }
            else { f0 = make_float4(0.f, 0.f, 0.f, 0.f); f1 = f0; }
            float f[8] = {f0.x, f0.y, f0.z, f0.w, f1.x, f1.y, f1.z, f1.w};
            uint32_t hw[4], lw[4];
#pragma unroll
            for (int j = 0; j < 4; j++) {
                __nv_bfloat16 h0 = __float2bfloat16_rn(f[2 * j]);
                __nv_bfloat16 h1 = __float2bfloat16_rn(f[2 * j + 1]);
                __nv_bfloat16 l0 = __float2bfloat16_rn(f[2 * j]     - __bfloat162float(h0));
                __nv_bfloat16 l1 = __float2bfloat16_rn(f[2 * j + 1] - __bfloat162float(h1));
                hw[j] = (uint32_t)__bfloat16_as_ushort(h0) | ((uint32_t)__bfloat16_as_ushort(h1) << 16);
                lw[j] = (uint32_t)__bfloat16_as_ushort(l0) | ((uint32_t)__bfloat16_as_ushort(l1) << 16);
            }
            dH[g] = make_uint4(hw[0], hw[1], hw[2], hw[3]);
            dL[g] = make_uint4(lw[0], lw[1], lw[2], lw[3]);
        }
    }
    __syncthreads();

    // ---- warp tiling: 2(m) x 4(n); warp tile 64 rows x 32 cols ----
    const int wm = wid & 1;          // 0..1
    const int wn = wid >> 1;         // 0..3
    const int wrow = wm * 64;        // warp row offset in tile
    const int wcol = wn * 32;        // warp col offset in tile

    float acc[4][4][4];
#pragma unroll
    for (int mt = 0; mt < 4; mt++)
#pragma unroll
        for (int nt = 0; nt < 4; nt++)
#pragma unroll
            for (int j = 0; j < 4; j++) acc[mt][nt][j] = 0.0f;

    // ldmatrix per-lane row/col selectors
    const int a_r   = (lane & 7) | (lane & 8);        // 0..15
    const int a_ko  = (lane & 16) ? 8 : 0;
    const int b_n   = (lane & 7) | ((lane & 16) >> 1); // 0..15
    const int b_ko  = (lane & 8) ? 8 : 0;

    uint32_t xs_hi_s = (uint32_t)__cvta_generic_to_shared(xs_hi);
    uint32_t xs_lo_s = (uint32_t)__cvta_generic_to_shared(xs_lo);
    uint32_t ws_hi_s = (uint32_t)__cvta_generic_to_shared(ws_hi);
    uint32_t ws_lo_s = (uint32_t)__cvta_generic_to_shared(ws_lo);

#pragma unroll
    for (int pass = 0; pass < 3; pass++) {
        uint32_t abase = (pass == 2) ? xs_lo_s : xs_hi_s;   // Xlo only in pass 2
        uint32_t bbase = (pass == 1) ? ws_lo_s : ws_hi_s;   // Wlo only in pass 1
#pragma unroll
        for (int ks = 0; ks < 8; ks++) {
            const int k0 = ks * 16;
            uint32_t a[4][4];
#pragma unroll
            for (int mt = 0; mt < 4; mt++) {
                uint32_t addr = abase + (((wrow + mt * 16 + a_r) * SX + k0 + a_ko) << 1);
                ldsm_x4(addr, a[mt][0], a[mt][1], a[mt][2], a[mt][3]);
            }
            uint32_t b[4][2];
#pragma unroll
            for (int np = 0; np < 2; np++) {
                uint32_t addr = bbase + (((wcol + np * 16 + b_n) * SX + k0 + b_ko) << 1);
                uint32_t r0, r1, r2, r3;
                ldsm_x4(addr, r0, r1, r2, r3);
                b[2 * np][0] = r0; b[2 * np][1] = r1;
                b[2 * np + 1][0] = r2; b[2 * np + 1][1] = r3;
            }
#pragma unroll
            for (int mt = 0; mt < 4; mt++)
#pragma unroll
                for (int nt = 0; nt < 4; nt++)
                    mma16816(acc[mt][nt], a[mt], b[nt]);
        }
    }

    // ---- epilogue: scale by rsqrt(sdeg+EPS), store float2 pairs ----
    const int g  = lane >> 2;
    const int tg = lane & 3;
#pragma unroll
    for (int mt = 0; mt < 4; mt++) {
        int r_lo = row0 + wrow + mt * 16 + g;
        int r_hi = r_lo + 8;
        float sc_lo = (r_lo < N) ? rsqrtf((float)g_sdeg[r_lo] + EPS) : 0.0f;
        float sc_hi = (r_hi < N) ? rsqrtf((float)g_sdeg[r_hi] + EPS) : 0.0f;
#pragma unroll
        for (int nt = 0; nt < 4; nt++) {
            int col = wcol + nt * 8 + tg * 2;
            if (r_lo < N) {
                float2* p = reinterpret_cast<float2*>(g_y + (size_t)r_lo * 128 + col);
                *p = make_float2(acc[mt][nt][0] * sc_lo, acc[mt][nt][1] * sc_lo);
            }
            if (r_hi < N) {
                float2* p = reinterpret_cast<float2*>(g_y + (size_t)r_hi * 128 + col);
                *p = make_float2(acc[mt][nt][2] * sc_hi, acc[mt][nt][3] * sc_hi);
            }
        }
    }
}

// ---------------------------------------------------------------------------
// K6: gather  out[n] = dst_inv[n] * sum_{e: dst=n} y[src_e] + bias
// ---------------------------------------------------------------------------
__global__ __launch_bounds__(256) void gather_kernel(float* __restrict__ out,
                                                     const float* __restrict__ bias,
                                                     int N) {
    int n = (blockIdx.x * blockDim.x + threadIdx.x) >> 5;
    int lane = threadIdx.x & 31;
    if (n >= N) return;

    int off = g_off[n];
    int cnt = g_ddeg[n];

    const float4* yp = reinterpret_cast<const float4*>(g_y);
    float4 acc = make_float4(0.f, 0.f, 0.f, 0.f);

    int i = 0;
    for (; i + 4 <= cnt; i += 4) {
        int s0 = __ldg(&g_csr[off + i + 0]);
        int s1 = __ldg(&g_csr[off + i + 1]);
        int s2 = __ldg(&g_csr[off + i + 2]);
        int s3 = __ldg(&g_csr[off + i + 3]);
        float4 v0 = yp[(size_t)s0 * 32 + lane];
        float4 v1 = yp[(size_t)s1 * 32 + lane];
        float4 v2 = yp[(size_t)s2 * 32 + lane];
        float4 v3 = yp[(size_t)s3 * 32 + lane];
        acc.x += v0.x + v1.x + v2.x + v3.x;
        acc.y += v0.y + v1.y + v2.y + v3.y;
        acc.z += v0.z + v1.z + v2.z + v3.z;
        acc.w += v0.w + v1.w + v2.w + v3.w;
    }
    for (; i < cnt; i++) {
        int s = __ldg(&g_csr[off + i]);
        float4 v = yp[(size_t)s * 32 + lane];
        acc.x += v.x; acc.y += v.y; acc.z += v.z; acc.w += v.w;
    }

    float dinv = rsqrtf((float)cnt + EPS);
    const float4 b = reinterpret_cast<const float4*>(bias)[lane];
    float4 r = make_float4(acc.x * dinv + b.x, acc.y * dinv + b.y,
                           acc.z * dinv + b.z, acc.w * dinv + b.w);
    reinterpret_cast<float4*>(out)[(size_t)n * 32 + lane] = r;
}

// ---------------------------------------------------------------------------
extern "C" void kernel_launch(void* const* d_in, const int* in_sizes, int n_in,
                              void* d_out, int out_size) {
    const float* x    = (const float*)d_in[0];
    const int*   ei   = (const int*)d_in[1];
    const float* w    = (const float*)d_in[2];
    const float* bias = (const float*)d_in[3];
    float*       out  = (float*)d_out;

    const int N = in_sizes[0] / C;
    const int E = in_sizes[1] / 2;

    cudaFuncSetAttribute(gemm_tc_kernel, cudaFuncAttributeMaxDynamicSharedMemorySize, SMEM_GEMM);

    prep_w_kernel<<<(128 * SX + 255) / 256, 256>>>(w);
    zero_kernel<<<(N + 255) / 256, 256>>>(N);
    deg_kernel<<<(E + 255) / 256, 256>>>(ei, E);
    int nb = (N + 1023) / 1024;
    scanA_kernel<<<nb, 1024>>>(N);
    scanB_kernel<<<1, 64>>>(nb);
    scanC_kernel<<<(N + 255) / 256, 256>>>(N);
    fill_kernel<<<(E + 255) / 256, 256>>>(ei, E);
    gemm_tc_kernel<<<(N + 127) / 128, 256, SMEM_GEMM>>>(x, N);
    {
        long long total_threads = (long long)N * 32;
        int blocks = (int)((total_threads + 255) / 256);
        gather_kernel<<<blocks, 256>>>(out, bias, N);
    }
}

// round 6
// speedup vs baseline: 1.9167x; 1.0141x over previous
#include <cuda_runtime.h>
#include <cuda_bf16.h>
#include <cstdint>

#define C 128
#define MAX_N 50176
#define MAX_E 1050000
#define EPS 1e-6f
#define SX 136                      // padded bf16 row stride (272B: conflict-free ldmatrix)

// ---------------------------------------------------------------------------
// Device scratch
// ---------------------------------------------------------------------------
__device__ __align__(16) float g_y[MAX_N * C];     // (x @ W) * src_inv[row]
__device__ int   g_sdeg[MAX_N];
__device__ int   g_ddeg[MAX_N];
__device__ int   g_off[MAX_N];
__device__ int   g_cur[MAX_N];
__device__ int   g_csr[MAX_E];
__device__ int   g_btot[64];
// W transposed (Wt[n][k]) as bf16 hi/lo, padded stride SX
__device__ __align__(16) unsigned short g_wt_hi[128 * SX];
__device__ __align__(16) unsigned short g_wt_lo[128 * SX];

// ---------------------------------------------------------------------------
// K1: fused prep: Wt hi/lo conversion + zero degree arrays
// ---------------------------------------------------------------------------
__global__ void prep_kernel(const float* __restrict__ w, int N) {
    int tid = blockIdx.x * blockDim.x + threadIdx.x;
    if (tid < 128 * SX) {
        int n = tid / SX, k = tid % SX;
        unsigned short h = 0, l = 0;
        if (k < 128) {
            float f = w[k * 128 + n];
            __nv_bfloat16 hb = __float2bfloat16_rn(f);
            __nv_bfloat16 lb = __float2bfloat16_rn(f - __bfloat162float(hb));
            h = __bfloat16_as_ushort(hb);
            l = __bfloat16_as_ushort(lb);
        }
        g_wt_hi[tid] = h;
        g_wt_lo[tid] = l;
    }
    if (tid < N) { g_sdeg[tid] = 0; g_ddeg[tid] = 0; }
}

// ---------------------------------------------------------------------------
// K2: degree counts, 4 edges per thread (int4 loads, 8 independent atomics)
// ---------------------------------------------------------------------------
__global__ void deg_kernel(const int* __restrict__ ei, int E) {
    int e0 = (blockIdx.x * blockDim.x + threadIdx.x) * 4;
    if (e0 >= E) return;
    if (e0 + 4 <= E) {
        int4 s = *reinterpret_cast<const int4*>(ei + e0);
        int4 d = *reinterpret_cast<const int4*>(ei + E + e0);
        atomicAdd(&g_sdeg[s.x], 1); atomicAdd(&g_sdeg[s.y], 1);
        atomicAdd(&g_sdeg[s.z], 1); atomicAdd(&g_sdeg[s.w], 1);
        atomicAdd(&g_ddeg[d.x], 1); atomicAdd(&g_ddeg[d.y], 1);
        atomicAdd(&g_ddeg[d.z], 1); atomicAdd(&g_ddeg[d.w], 1);
    } else {
        for (int e = e0; e < E; e++) {
            atomicAdd(&g_sdeg[ei[e]], 1);
            atomicAdd(&g_ddeg[ei[E + e]], 1);
        }
    }
}

// ---------------------------------------------------------------------------
// K3: scanA — per-1024-chunk local exclusive scan + chunk totals
// ---------------------------------------------------------------------------
__global__ __launch_bounds__(1024) void scanA_kernel(int N) {
    __shared__ int wt[32], wp[32];
    int tid = threadIdx.x, lane = tid & 31, wid = tid >> 5;
    int i = blockIdx.x * 1024 + tid;
    int v = (i < N) ? g_ddeg[i] : 0;
    int incl = v;
#pragma unroll
    for (int d = 1; d < 32; d <<= 1) {
        int t = __shfl_up_sync(0xffffffff, incl, d);
        if (lane >= d) incl += t;
    }
    if (lane == 31) wt[wid] = incl;
    __syncthreads();
    if (wid == 0) {
        int wv = wt[lane];
        int wi = wv;
#pragma unroll
        for (int d = 1; d < 32; d <<= 1) {
            int t = __shfl_up_sync(0xffffffff, wi, d);
            if (lane >= d) wi += t;
        }
        wp[lane] = wi - wv;
        if (lane == 31) g_btot[blockIdx.x] = wi;
    }
    __syncthreads();
    if (i < N) g_off[i] = wp[wid] + incl - v;
}

// ---------------------------------------------------------------------------
// K4: scanC — add chunk prefix (computed in-block from g_btot) and init cursors
// ---------------------------------------------------------------------------
__global__ void scanC_kernel(int N) {
    __shared__ int s_pre;
    int i = blockIdx.x * blockDim.x + threadIdx.x;
    int chunk = (blockIdx.x * blockDim.x) >> 10;    // this block's 1024-chunk (nb<=49)
    if (threadIdx.x < 32) {
        int t = threadIdx.x;
        int v = (t < chunk) ? g_btot[t] : 0;
        if (t + 32 < chunk) v += g_btot[t + 32];
#pragma unroll
        for (int d = 16; d > 0; d >>= 1) v += __shfl_down_sync(0xffffffff, v, d);
        if (t == 0) s_pre = v;
    }
    __syncthreads();
    if (i >= N) return;
    int v = g_off[i] + s_pre;
    g_off[i] = v;
    g_cur[i] = v;
}

// ---------------------------------------------------------------------------
// K5: fill CSR, 4 edges per thread (cursors pre-initialized to offsets)
// ---------------------------------------------------------------------------
__global__ void fill_kernel(const int* __restrict__ ei, int E) {
    int e0 = (blockIdx.x * blockDim.x + threadIdx.x) * 4;
    if (e0 >= E) return;
    if (e0 + 4 <= E) {
        int4 s = *reinterpret_cast<const int4*>(ei + e0);
        int4 d = *reinterpret_cast<const int4*>(ei + E + e0);
        int p0 = atomicAdd(&g_cur[d.x], 1);
        int p1 = atomicAdd(&g_cur[d.y], 1);
        int p2 = atomicAdd(&g_cur[d.z], 1);
        int p3 = atomicAdd(&g_cur[d.w], 1);
        g_csr[p0] = s.x; g_csr[p1] = s.y; g_csr[p2] = s.z; g_csr[p3] = s.w;
    } else {
        for (int e = e0; e < E; e++) {
            int pos = atomicAdd(&g_cur[ei[E + e]], 1);
            g_csr[pos] = ei[e];
        }
    }
}

// ---------------------------------------------------------------------------
// K6: tensor-core GEMM via mma.sync (HMMA), bf16 hi/lo x3 passes, fp32 accum.
//     y = (x @ W) * rsqrt(sdeg+EPS). CTA 128x128, 8 warps = 2(m) x 4(n).
// ---------------------------------------------------------------------------
#define SMEM_GEMM (4 * 128 * SX * 2)   // 139264 B

__device__ __forceinline__ void ldsm_x4(uint32_t addr, uint32_t& r0, uint32_t& r1,
                                        uint32_t& r2, uint32_t& r3) {
    asm volatile("ldmatrix.sync.aligned.m8n8.x4.shared.b16 {%0,%1,%2,%3}, [%4];"
                 : "=r"(r0), "=r"(r1), "=r"(r2), "=r"(r3) : "r"(addr));
}

__device__ __forceinline__ void mma16816(float* c, const uint32_t* a, const uint32_t* b) {
    asm volatile(
        "mma.sync.aligned.m16n8k16.row.col.f32.bf16.bf16.f32 "
        "{%0,%1,%2,%3}, {%4,%5,%6,%7}, {%8,%9}, {%0,%1,%2,%3};"
        : "+f"(c[0]), "+f"(c[1]), "+f"(c[2]), "+f"(c[3])
        : "r"(a[0]), "r"(a[1]), "r"(a[2]), "r"(a[3]), "r"(b[0]), "r"(b[1]));
}

__global__ __launch_bounds__(256, 1) void gemm_tc_kernel(const float* __restrict__ x,
                                                         int N) {
    extern __shared__ __align__(16) char smem[];
    unsigned short* xs_hi = reinterpret_cast<unsigned short*>(smem);
    unsigned short* xs_lo = xs_hi + 128 * SX;
    unsigned short* ws_hi = xs_lo + 128 * SX;
    unsigned short* ws_lo = ws_hi + 128 * SX;

    const int tid = threadIdx.x;
    const int lane = tid & 31;
    const int wid = tid >> 5;
    const int row0 = blockIdx.x * 128;

    // ---- stage W (copy padded hi/lo images) ----
    {
        const uint4* sH = reinterpret_cast<const uint4*>(g_wt_hi);
        const uint4* sL = reinterpret_cast<const uint4*>(g_wt_lo);
        uint4* dH = reinterpret_cast<uint4*>(ws_hi);
        uint4* dL = reinterpret_cast<uint4*>(ws_lo);
        const int n16 = 128 * SX / 8;   // 2176 uint4
        for (int i = tid; i < n16; i += 256) { dH[i] = sH[i]; dL[i] = sL[i]; }
    }

    // ---- stage x tile -> bf16 hi/lo (thread = half row) ----
    {
        int r = tid >> 1, h = tid & 1;
        int gr = row0 + r;
        const float4* xrow = reinterpret_cast<const float4*>(x + (size_t)gr * 128 + h * 64);
        uint4* dH = reinterpret_cast<uint4*>(xs_hi + r * SX + h * 64);
        uint4* dL = reinterpret_cast<uint4*>(xs_lo + r * SX + h * 64);
#pragma unroll
        for (int g = 0; g < 8; g++) {
            float4 f0, f1;
            if (gr < N) { f0 = xrow[2 * g]; f1 = xrow[2 * g + 1]; }
            else { f0 = make_float4(0.f, 0.f, 0.f, 0.f); f1 = f0; }
            float f[8] = {f0.x, f0.y, f0.z, f0.w, f1.x, f1.y, f1.z, f1.w};
            uint32_t hw[4], lw[4];
#pragma unroll
            for (int j = 0; j < 4; j++) {
                __nv_bfloat16 h0 = __float2bfloat16_rn(f[2 * j]);
                __nv_bfloat16 h1 = __float2bfloat16_rn(f[2 * j + 1]);
                __nv_bfloat16 l0 = __float2bfloat16_rn(f[2 * j]     - __bfloat162float(h0));
                __nv_bfloat16 l1 = __float2bfloat16_rn(f[2 * j + 1] - __bfloat162float(h1));
                hw[j] = (uint32_t)__bfloat16_as_ushort(h0) | ((uint32_t)__bfloat16_as_ushort(h1) << 16);
                lw[j] = (uint32_t)__bfloat16_as_ushort(l0) | ((uint32_t)__bfloat16_as_ushort(l1) << 16);
            }
            dH[g] = make_uint4(hw[0], hw[1], hw[2], hw[3]);
            dL[g] = make_uint4(lw[0], lw[1], lw[2], lw[3]);
        }
    }
    __syncthreads();

    // ---- warp tiling: 2(m) x 4(n); warp tile 64 rows x 32 cols ----
    const int wm = wid & 1;
    const int wn = wid >> 1;
    const int wrow = wm * 64;
    const int wcol = wn * 32;

    float acc[4][4][4];
#pragma unroll
    for (int mt = 0; mt < 4; mt++)
#pragma unroll
        for (int nt = 0; nt < 4; nt++)
#pragma unroll
            for (int j = 0; j < 4; j++) acc[mt][nt][j] = 0.0f;

    const int a_r   = (lane & 7) | (lane & 8);
    const int a_ko  = (lane & 16) ? 8 : 0;
    const int b_n   = (lane & 7) | ((lane & 16) >> 1);
    const int b_ko  = (lane & 8) ? 8 : 0;

    uint32_t xs_hi_s = (uint32_t)__cvta_generic_to_shared(xs_hi);
    uint32_t xs_lo_s = (uint32_t)__cvta_generic_to_shared(xs_lo);
    uint32_t ws_hi_s = (uint32_t)__cvta_generic_to_shared(ws_hi);
    uint32_t ws_lo_s = (uint32_t)__cvta_generic_to_shared(ws_lo);

#pragma unroll
    for (int pass = 0; pass < 3; pass++) {
        uint32_t abase = (pass == 2) ? xs_lo_s : xs_hi_s;
        uint32_t bbase = (pass == 1) ? ws_lo_s : ws_hi_s;
#pragma unroll
        for (int ks = 0; ks < 8; ks++) {
            const int k0 = ks * 16;
            uint32_t a[4][4];
#pragma unroll
            for (int mt = 0; mt < 4; mt++) {
                uint32_t addr = abase + (((wrow + mt * 16 + a_r) * SX + k0 + a_ko) << 1);
                ldsm_x4(addr, a[mt][0], a[mt][1], a[mt][2], a[mt][3]);
            }
            uint32_t b[4][2];
#pragma unroll
            for (int np = 0; np < 2; np++) {
                uint32_t addr = bbase + (((wcol + np * 16 + b_n) * SX + k0 + b_ko) << 1);
                uint32_t r0, r1, r2, r3;
                ldsm_x4(addr, r0, r1, r2, r3);
                b[2 * np][0] = r0; b[2 * np][1] = r1;
                b[2 * np + 1][0] = r2; b[2 * np + 1][1] = r3;
            }
#pragma unroll
            for (int mt = 0; mt < 4; mt++)
#pragma unroll
                for (int nt = 0; nt < 4; nt++)
                    mma16816(acc[mt][nt], a[mt], b[nt]);
        }
    }

    // ---- epilogue: scale by rsqrt(sdeg+EPS), store float2 pairs ----
    const int g  = lane >> 2;
    const int tg = lane & 3;
#pragma unroll
    for (int mt = 0; mt < 4; mt++) {
        int r_lo = row0 + wrow + mt * 16 + g;
        int r_hi = r_lo + 8;
        float sc_lo = (r_lo < N) ? rsqrtf((float)g_sdeg[r_lo] + EPS) : 0.0f;
        float sc_hi = (r_hi < N) ? rsqrtf((float)g_sdeg[r_hi] + EPS) : 0.0f;
#pragma unroll
        for (int nt = 0; nt < 4; nt++) {
            int col = wcol + nt * 8 + tg * 2;
            if (r_lo < N) {
                float2* p = reinterpret_cast<float2*>(g_y + (size_t)r_lo * 128 + col);
                *p = make_float2(acc[mt][nt][0] * sc_lo, acc[mt][nt][1] * sc_lo);
            }
            if (r_hi < N) {
                float2* p = reinterpret_cast<float2*>(g_y + (size_t)r_hi * 128 + col);
                *p = make_float2(acc[mt][nt][2] * sc_hi, acc[mt][nt][3] * sc_hi);
            }
        }
    }
}

// ---------------------------------------------------------------------------
// K7: gather  out[n] = dst_inv[n] * sum_{e: dst=n} y[src_e] + bias
// ---------------------------------------------------------------------------
__global__ __launch_bounds__(256) void gather_kernel(float* __restrict__ out,
                                                     const float* __restrict__ bias,
                                                     int N) {
    int n = (blockIdx.x * blockDim.x + threadIdx.x) >> 5;
    int lane = threadIdx.x & 31;
    if (n >= N) return;

    int off = g_off[n];
    int cnt = g_ddeg[n];

    const float4* yp = reinterpret_cast<const float4*>(g_y);
    float4 acc = make_float4(0.f, 0.f, 0.f, 0.f);

    int i = 0;
    for (; i + 4 <= cnt; i += 4) {
        int s0 = __ldg(&g_csr[off + i + 0]);
        int s1 = __ldg(&g_csr[off + i + 1]);
        int s2 = __ldg(&g_csr[off + i + 2]);
        int s3 = __ldg(&g_csr[off + i + 3]);
        float4 v0 = yp[(size_t)s0 * 32 + lane];
        float4 v1 = yp[(size_t)s1 * 32 + lane];
        float4 v2 = yp[(size_t)s2 * 32 + lane];
        float4 v3 = yp[(size_t)s3 * 32 + lane];
        acc.x += v0.x + v1.x + v2.x + v3.x;
        acc.y += v0.y + v1.y + v2.y + v3.y;
        acc.z += v0.z + v1.z + v2.z + v3.z;
        acc.w += v0.w + v1.w + v2.w + v3.w;
    }
    for (; i < cnt; i++) {
        int s = __ldg(&g_csr[off + i]);
        float4 v = yp[(size_t)s * 32 + lane];
        acc.x += v.x; acc.y += v.y; acc.z += v.z; acc.w += v.w;
    }

    float dinv = rsqrtf((float)cnt + EPS);
    const float4 b = reinterpret_cast<const float4*>(bias)[lane];
    float4 r = make_float4(acc.x * dinv + b.x, acc.y * dinv + b.y,
                           acc.z * dinv + b.z, acc.w * dinv + b.w);
    reinterpret_cast<float4*>(out)[(size_t)n * 32 + lane] = r;
}

// ---------------------------------------------------------------------------
extern "C" void kernel_launch(void* const* d_in, const int* in_sizes, int n_in,
                              void* d_out, int out_size) {
    const float* x    = (const float*)d_in[0];
    const int*   ei   = (const int*)d_in[1];
    const float* w    = (const float*)d_in[2];
    const float* bias = (const float*)d_in[3];
    float*       out  = (float*)d_out;

    const int N = in_sizes[0] / C;
    const int E = in_sizes[1] / 2;

    cudaFuncSetAttribute(gemm_tc_kernel, cudaFuncAttributeMaxDynamicSharedMemorySize, SMEM_GEMM);

    int prep_n = (128 * SX > N) ? 128 * SX : N;
    prep_kernel<<<(prep_n + 255) / 256, 256>>>(w, N);
    deg_kernel<<<((E + 3) / 4 + 255) / 256, 256>>>(ei, E);
    int nb = (N + 1023) / 1024;
    scanA_kernel<<<nb, 1024>>>(N);
    scanC_kernel<<<(N + 255) / 256, 256>>>(N);
    fill_kernel<<<((E + 3) / 4 + 255) / 256, 256>>>(ei, E);
    gemm_tc_kernel<<<(N + 127) / 128, 256, SMEM_GEMM>>>(x, N);
    {
        long long total_threads = (long long)N * 32;
        int blocks = (int)((total_threads + 255) / 256);
        gather_kernel<<<blocks, 256>>>(out, bias, N);
    }
}

// round 7
// speedup vs baseline: 2.0050x; 1.0461x over previous
#include <cuda_runtime.h>
#include <cuda_bf16.h>
#include <cuda_fp16.h>
#include <cstdint>

#define C 128
#define MAX_N 50176
#define MAX_E 1050000
#define EPS 1e-6f
#define SX 136                      // padded bf16 row stride (272B: conflict-free ldmatrix)

// ---------------------------------------------------------------------------
// Device scratch
// ---------------------------------------------------------------------------
__device__ __align__(16) __half g_yh[MAX_N * C];   // fp16: (x @ W) * src_inv[row]
__device__ int   g_sdeg[MAX_N];
__device__ int   g_ddeg[MAX_N];
__device__ int   g_off[MAX_N];
__device__ int   g_cur[MAX_N];
__device__ int   g_csr[MAX_E];
__device__ int   g_btot[64];
// W transposed (Wt[n][k]) as bf16 hi/lo, padded stride SX
__device__ __align__(16) unsigned short g_wt_hi[128 * SX];
__device__ __align__(16) unsigned short g_wt_lo[128 * SX];

// ---------------------------------------------------------------------------
// K1: fused prep: Wt hi/lo conversion + zero degree arrays
// ---------------------------------------------------------------------------
__global__ void prep_kernel(const float* __restrict__ w, int N) {
    int tid = blockIdx.x * blockDim.x + threadIdx.x;
    if (tid < 128 * SX) {
        int n = tid / SX, k = tid % SX;
        unsigned short h = 0, l = 0;
        if (k < 128) {
            float f = w[k * 128 + n];
            __nv_bfloat16 hb = __float2bfloat16_rn(f);
            __nv_bfloat16 lb = __float2bfloat16_rn(f - __bfloat162float(hb));
            h = __bfloat16_as_ushort(hb);
            l = __bfloat16_as_ushort(lb);
        }
        g_wt_hi[tid] = h;
        g_wt_lo[tid] = l;
    }
    if (tid < N) { g_sdeg[tid] = 0; g_ddeg[tid] = 0; }
}

// ---------------------------------------------------------------------------
// K2: degree counts, 4 edges per thread
// ---------------------------------------------------------------------------
__global__ void deg_kernel(const int* __restrict__ ei, int E) {
    int e0 = (blockIdx.x * blockDim.x + threadIdx.x) * 4;
    if (e0 >= E) return;
    if (((E & 3) == 0) && (e0 + 4 <= E)) {
        int4 s = *reinterpret_cast<const int4*>(ei + e0);
        int4 d = *reinterpret_cast<const int4*>(ei + E + e0);
        atomicAdd(&g_sdeg[s.x], 1); atomicAdd(&g_sdeg[s.y], 1);
        atomicAdd(&g_sdeg[s.z], 1); atomicAdd(&g_sdeg[s.w], 1);
        atomicAdd(&g_ddeg[d.x], 1); atomicAdd(&g_ddeg[d.y], 1);
        atomicAdd(&g_ddeg[d.z], 1); atomicAdd(&g_ddeg[d.w], 1);
    } else {
        int e1 = (e0 + 4 < E) ? e0 + 4 : E;
        for (int e = e0; e < e1; e++) {
            atomicAdd(&g_sdeg[ei[e]], 1);
            atomicAdd(&g_ddeg[ei[E + e]], 1);
        }
    }
}

// ---------------------------------------------------------------------------
// K3: scanA — per-1024-chunk local exclusive scan + chunk totals
// ---------------------------------------------------------------------------
__global__ __launch_bounds__(1024) void scanA_kernel(int N) {
    __shared__ int wt[32], wp[32];
    int tid = threadIdx.x, lane = tid & 31, wid = tid >> 5;
    int i = blockIdx.x * 1024 + tid;
    int v = (i < N) ? g_ddeg[i] : 0;
    int incl = v;
#pragma unroll
    for (int d = 1; d < 32; d <<= 1) {
        int t = __shfl_up_sync(0xffffffff, incl, d);
        if (lane >= d) incl += t;
    }
    if (lane == 31) wt[wid] = incl;
    __syncthreads();
    if (wid == 0) {
        int wv = wt[lane];
        int wi = wv;
#pragma unroll
        for (int d = 1; d < 32; d <<= 1) {
            int t = __shfl_up_sync(0xffffffff, wi, d);
            if (lane >= d) wi += t;
        }
        wp[lane] = wi - wv;
        if (lane == 31) g_btot[blockIdx.x] = wi;
    }
    __syncthreads();
    if (i < N) g_off[i] = wp[wid] + incl - v;
}

// ---------------------------------------------------------------------------
// K4: scanC — add chunk prefix (computed in-block from g_btot) and init cursors
// ---------------------------------------------------------------------------
__global__ void scanC_kernel(int N) {
    __shared__ int s_pre;
    int i = blockIdx.x * blockDim.x + threadIdx.x;
    int chunk = (blockIdx.x * blockDim.x) >> 10;
    if (threadIdx.x < 32) {
        int t = threadIdx.x;
        int v = (t < chunk) ? g_btot[t] : 0;
        if (t + 32 < chunk) v += g_btot[t + 32];
#pragma unroll
        for (int d = 16; d > 0; d >>= 1) v += __shfl_down_sync(0xffffffff, v, d);
        if (t == 0) s_pre = v;
    }
    __syncthreads();
    if (i >= N) return;
    int v = g_off[i] + s_pre;
    g_off[i] = v;
    g_cur[i] = v;
}

// ---------------------------------------------------------------------------
// K5: fill CSR, 4 edges per thread (cursors pre-initialized to offsets)
// ---------------------------------------------------------------------------
__global__ void fill_kernel(const int* __restrict__ ei, int E) {
    int e0 = (blockIdx.x * blockDim.x + threadIdx.x) * 4;
    if (e0 >= E) return;
    if (((E & 3) == 0) && (e0 + 4 <= E)) {
        int4 s = *reinterpret_cast<const int4*>(ei + e0);
        int4 d = *reinterpret_cast<const int4*>(ei + E + e0);
        int p0 = atomicAdd(&g_cur[d.x], 1);
        int p1 = atomicAdd(&g_cur[d.y], 1);
        int p2 = atomicAdd(&g_cur[d.z], 1);
        int p3 = atomicAdd(&g_cur[d.w], 1);
        g_csr[p0] = s.x; g_csr[p1] = s.y; g_csr[p2] = s.z; g_csr[p3] = s.w;
    } else {
        int e1 = (e0 + 4 < E) ? e0 + 4 : E;
        for (int e = e0; e < e1; e++) {
            int pos = atomicAdd(&g_cur[ei[E + e]], 1);
            g_csr[pos] = ei[e];
        }
    }
}

// ---------------------------------------------------------------------------
// K6: tensor-core GEMM via mma.sync (HMMA), bf16 hi/lo x3 passes, fp32 accum.
//     y' = (x @ W) * rsqrt(sdeg+EPS) stored as fp16. CTA 128x128, 8 warps.
// ---------------------------------------------------------------------------
#define SMEM_GEMM (4 * 128 * SX * 2)   // 139264 B

__device__ __forceinline__ void ldsm_x4(uint32_t addr, uint32_t& r0, uint32_t& r1,
                                        uint32_t& r2, uint32_t& r3) {
    asm volatile("ldmatrix.sync.aligned.m8n8.x4.shared.b16 {%0,%1,%2,%3}, [%4];"
                 : "=r"(r0), "=r"(r1), "=r"(r2), "=r"(r3) : "r"(addr));
}

__device__ __forceinline__ void mma16816(float* c, const uint32_t* a, const uint32_t* b) {
    asm volatile(
        "mma.sync.aligned.m16n8k16.row.col.f32.bf16.bf16.f32 "
        "{%0,%1,%2,%3}, {%4,%5,%6,%7}, {%8,%9}, {%0,%1,%2,%3};"
        : "+f"(c[0]), "+f"(c[1]), "+f"(c[2]), "+f"(c[3])
        : "r"(a[0]), "r"(a[1]), "r"(a[2]), "r"(a[3]), "r"(b[0]), "r"(b[1]));
}

__global__ __launch_bounds__(256, 1) void gemm_tc_kernel(const float* __restrict__ x,
                                                         int N) {
    extern __shared__ __align__(16) char smem[];
    unsigned short* xs_hi = reinterpret_cast<unsigned short*>(smem);
    unsigned short* xs_lo = xs_hi + 128 * SX;
    unsigned short* ws_hi = xs_lo + 128 * SX;
    unsigned short* ws_lo = ws_hi + 128 * SX;

    const int tid = threadIdx.x;
    const int lane = tid & 31;
    const int wid = tid >> 5;
    const int row0 = blockIdx.x * 128;

    // ---- stage W (copy padded hi/lo images) ----
    {
        const uint4* sH = reinterpret_cast<const uint4*>(g_wt_hi);
        const uint4* sL = reinterpret_cast<const uint4*>(g_wt_lo);
        uint4* dH = reinterpret_cast<uint4*>(ws_hi);
        uint4* dL = reinterpret_cast<uint4*>(ws_lo);
        const int n16 = 128 * SX / 8;
        for (int i = tid; i < n16; i += 256) { dH[i] = sH[i]; dL[i] = sL[i]; }
    }

    // ---- stage x tile -> bf16 hi/lo (thread = half row) ----
    {
        int r = tid >> 1, h = tid & 1;
        int gr = row0 + r;
        const float4* xrow = reinterpret_cast<const float4*>(x + (size_t)gr * 128 + h * 64);
        uint4* dH = reinterpret_cast<uint4*>(xs_hi + r * SX + h * 64);
        uint4* dL = reinterpret_cast<uint4*>(xs_lo + r * SX + h * 64);
#pragma unroll
        for (int g = 0; g < 8; g++) {
            float4 f0, f1;
            if (gr < N) { f0 = xrow[2 * g]; f1 = xrow[2 * g + 1]; }
            else { f0 = make_float4(0.f, 0.f, 0.f, 0.f); f1 = f0; }
            float f[8] = {f0.x, f0.y, f0.z, f0.w, f1.x, f1.y, f1.z, f1.w};
            uint32_t hw[4], lw[4];
#pragma unroll
            for (int j = 0; j < 4; j++) {
                __nv_bfloat16 h0 = __float2bfloat16_rn(f[2 * j]);
                __nv_bfloat16 h1 = __float2bfloat16_rn(f[2 * j + 1]);
                __nv_bfloat16 l0 = __float2bfloat16_rn(f[2 * j]     - __bfloat162float(h0));
                __nv_bfloat16 l1 = __float2bfloat16_rn(f[2 * j + 1] - __bfloat162float(h1));
                hw[j] = (uint32_t)__bfloat16_as_ushort(h0) | ((uint32_t)__bfloat16_as_ushort(h1) << 16);
                lw[j] = (uint32_t)__bfloat16_as_ushort(l0) | ((uint32_t)__bfloat16_as_ushort(l1) << 16);
            }
            dH[g] = make_uint4(hw[0], hw[1], hw[2], hw[3]);
            dL[g] = make_uint4(lw[0], lw[1], lw[2], lw[3]);
        }
    }
    __syncthreads();

    // ---- warp tiling: 2(m) x 4(n); warp tile 64 rows x 32 cols ----
    const int wm = wid & 1;
    const int wn = wid >> 1;
    const int wrow = wm * 64;
    const int wcol = wn * 32;

    float acc[4][4][4];
#pragma unroll
    for (int mt = 0; mt < 4; mt++)
#pragma unroll
        for (int nt = 0; nt < 4; nt++)
#pragma unroll
            for (int j = 0; j < 4; j++) acc[mt][nt][j] = 0.0f;

    const int a_r   = (lane & 7) | (lane & 8);
    const int a_ko  = (lane & 16) ? 8 : 0;
    const int b_n   = (lane & 7) | ((lane & 16) >> 1);
    const int b_ko  = (lane & 8) ? 8 : 0;

    uint32_t xs_hi_s = (uint32_t)__cvta_generic_to_shared(xs_hi);
    uint32_t xs_lo_s = (uint32_t)__cvta_generic_to_shared(xs_lo);
    uint32_t ws_hi_s = (uint32_t)__cvta_generic_to_shared(ws_hi);
    uint32_t ws_lo_s = (uint32_t)__cvta_generic_to_shared(ws_lo);

#pragma unroll
    for (int pass = 0; pass < 3; pass++) {
        uint32_t abase = (pass == 2) ? xs_lo_s : xs_hi_s;
        uint32_t bbase = (pass == 1) ? ws_lo_s : ws_hi_s;
#pragma unroll
        for (int ks = 0; ks < 8; ks++) {
            const int k0 = ks * 16;
            uint32_t a[4][4];
#pragma unroll
            for (int mt = 0; mt < 4; mt++) {
                uint32_t addr = abase + (((wrow + mt * 16 + a_r) * SX + k0 + a_ko) << 1);
                ldsm_x4(addr, a[mt][0], a[mt][1], a[mt][2], a[mt][3]);
            }
            uint32_t b[4][2];
#pragma unroll
            for (int np = 0; np < 2; np++) {
                uint32_t addr = bbase + (((wcol + np * 16 + b_n) * SX + k0 + b_ko) << 1);
                uint32_t r0, r1, r2, r3;
                ldsm_x4(addr, r0, r1, r2, r3);
                b[2 * np][0] = r0; b[2 * np][1] = r1;
                b[2 * np + 1][0] = r2; b[2 * np + 1][1] = r3;
            }
#pragma unroll
            for (int mt = 0; mt < 4; mt++)
#pragma unroll
                for (int nt = 0; nt < 4; nt++)
                    mma16816(acc[mt][nt], a[mt], b[nt]);
        }
    }

    // ---- epilogue: scale by rsqrt(sdeg+EPS), store fp16 pairs ----
    const int g  = lane >> 2;
    const int tg = lane & 3;
#pragma unroll
    for (int mt = 0; mt < 4; mt++) {
        int r_lo = row0 + wrow + mt * 16 + g;
        int r_hi = r_lo + 8;
        float sc_lo = (r_lo < N) ? rsqrtf((float)g_sdeg[r_lo] + EPS) : 0.0f;
        float sc_hi = (r_hi < N) ? rsqrtf((float)g_sdeg[r_hi] + EPS) : 0.0f;
#pragma unroll
        for (int nt = 0; nt < 4; nt++) {
            int col = wcol + nt * 8 + tg * 2;
            if (r_lo < N) {
                __half2* p = reinterpret_cast<__half2*>(g_yh + (size_t)r_lo * 128 + col);
                *p = __floats2half2_rn(acc[mt][nt][0] * sc_lo, acc[mt][nt][1] * sc_lo);
            }
            if (r_hi < N) {
                __half2* p = reinterpret_cast<__half2*>(g_yh + (size_t)r_hi * 128 + col);
                *p = __floats2half2_rn(acc[mt][nt][2] * sc_hi, acc[mt][nt][3] * sc_hi);
            }
        }
    }
}

// ---------------------------------------------------------------------------
// K7: gather  out[n] = dst_inv[n] * sum_{e: dst=n} y'[src_e] + bias
// One warp per node; lane l covers channels [4l, 4l+4) (uint2 = 4 halfs).
// ---------------------------------------------------------------------------
__global__ __launch_bounds__(256) void gather_kernel(float* __restrict__ out,
                                                     const float* __restrict__ bias,
                                                     int N) {
    int n = (blockIdx.x * blockDim.x + threadIdx.x) >> 5;
    int lane = threadIdx.x & 31;
    if (n >= N) return;

    int off = g_off[n];
    int cnt = g_ddeg[n];

    const uint2* yp = reinterpret_cast<const uint2*>(g_yh);   // 8B = 4 halfs
    float4 acc = make_float4(0.f, 0.f, 0.f, 0.f);

    int i = 0;
    for (; i + 4 <= cnt; i += 4) {
        int s0 = __ldg(&g_csr[off + i + 0]);
        int s1 = __ldg(&g_csr[off + i + 1]);
        int s2 = __ldg(&g_csr[off + i + 2]);
        int s3 = __ldg(&g_csr[off + i + 3]);
        uint2 u0 = yp[(size_t)s0 * 32 + lane];
        uint2 u1 = yp[(size_t)s1 * 32 + lane];
        uint2 u2 = yp[(size_t)s2 * 32 + lane];
        uint2 u3 = yp[(size_t)s3 * 32 + lane];
#pragma unroll
        for (int j = 0; j < 4; j++) {
            uint2 u = (j == 0) ? u0 : (j == 1) ? u1 : (j == 2) ? u2 : u3;
            float2 f0 = __half22float2(*reinterpret_cast<__half2*>(&u.x));
            float2 f1 = __half22float2(*reinterpret_cast<__half2*>(&u.y));
            acc.x += f0.x; acc.y += f0.y; acc.z += f1.x; acc.w += f1.y;
        }
    }
    for (; i < cnt; i++) {
        int s = __ldg(&g_csr[off + i]);
        uint2 u = yp[(size_t)s * 32 + lane];
        float2 f0 = __half22float2(*reinterpret_cast<__half2*>(&u.x));
        float2 f1 = __half22float2(*reinterpret_cast<__half2*>(&u.y));
        acc.x += f0.x; acc.y += f0.y; acc.z += f1.x; acc.w += f1.y;
    }

    float dinv = rsqrtf((float)cnt + EPS);
    const float4 b = reinterpret_cast<const float4*>(bias)[lane];
    float4 r = make_float4(acc.x * dinv + b.x, acc.y * dinv + b.y,
                           acc.z * dinv + b.z, acc.w * dinv + b.w);
    reinterpret_cast<float4*>(out)[(size_t)n * 32 + lane] = r;
}

// ---------------------------------------------------------------------------
extern "C" void kernel_launch(void* const* d_in, const int* in_sizes, int n_in,
                              void* d_out, int out_size) {
    const float* x    = (const float*)d_in[0];
    const int*   ei   = (const int*)d_in[1];
    const float* w    = (const float*)d_in[2];
    const float* bias = (const float*)d_in[3];
    float*       out  = (float*)d_out;

    const int N = in_sizes[0] / C;
    const int E = in_sizes[1] / 2;

    cudaFuncSetAttribute(gemm_tc_kernel, cudaFuncAttributeMaxDynamicSharedMemorySize, SMEM_GEMM);

    int prep_n = (128 * SX > N) ? 128 * SX : N;
    prep_kernel<<<(prep_n + 255) / 256, 256>>>(w, N);
    deg_kernel<<<((E + 3) / 4 + 255) / 256, 256>>>(ei, E);
    int nb = (N + 1023) / 1024;
    scanA_kernel<<<nb, 1024>>>(N);
    scanC_kernel<<<(N + 255) / 256, 256>>>(N);
    fill_kernel<<<((E + 3) / 4 + 255) / 256, 256>>>(ei, E);
    gemm_tc_kernel<<<(N + 127) / 128, 256, SMEM_GEMM>>>(x, N);
    {
        long long total_threads = (long long)N * 32;
        int blocks = (int)((total_threads + 255) / 256);
        gather_kernel<<<blocks, 256>>>(out, bias, N);
    }
}